// round 17
// baseline (speedup 1.0000x reference)
#include <cuda_runtime.h>
#include <cuda_bf16.h>
#include <cstdint>

// Problem constants
#define NB        512   // batch
#define NCQ       512   // cliques
#define KQ        4     // vars per clique
#define SQ        8     // states
#define HH        128   // hidden
#define BT        64    // batch rows per CTA tile
#define ROWS      256   // BT*KQ rows of h1 per CTA
#define NTHREADS  256
#define H1STR     68    // u32 row stride for sH1 (conflict-free LDS.32)
#define W2STR     72    // u32 row stride for sW2T/sW3T (conflict-free LDS.64)

// smem layout (bytes)
#define OFF_W2T   0                         // 128*72*4 = 36864
#define OFF_H1    36864                     // 256*68*4 = 69632 (full: 32 rows per warp)
#define OFF_B1    106496                    // 512
#define OFF_B2    107008                    // 512
#define OFF_B3    107520                    // 32
#define OFF_W3T   107552                    // 8*72*4 = 2304
#define OFF_XO    109856                    // 256 (char)
#define OFF_XP    110112                    // 256 (char)
#define OFF_LP    110368                    // 1024
#define SMEM_BYTES 111392                   // x2 CTAs = 222.8 KB <= 228 KB

// W1 pre-converted to bf16 (device global scratch: allowed, not a runtime alloc)
__device__ __nv_bfloat16 g_w1bf[(size_t)NCQ * 64 * HH];

__global__ void __launch_bounds__(256, 8)
conv_w1_kernel(const float* __restrict__ W1) {
    size_t i = (size_t)blockIdx.x * 256 + threadIdx.x;   // pair index
    // total pairs = 512*64*128/2 = 2,097,152
    float2 v = ((const float2*)W1)[i];
    ((__nv_bfloat162*)g_w1bf)[i] = __floats2bfloat162_rn(v.x, v.y);
}

static __device__ __forceinline__ void mma16816(float c[4], const unsigned a[4],
                                                unsigned b0, unsigned b1v) {
    asm volatile(
        "mma.sync.aligned.m16n8k16.row.col.f32.bf16.bf16.f32 "
        "{%0,%1,%2,%3}, {%4,%5,%6,%7}, {%8,%9}, {%0,%1,%2,%3};\n"
        : "+f"(c[0]), "+f"(c[1]), "+f"(c[2]), "+f"(c[3])
        : "r"(a[0]), "r"(a[1]), "r"(a[2]), "r"(a[3]), "r"(b0), "r"(b1v));
}

__global__ void __launch_bounds__(NTHREADS, 2)
jt_kernel(const int* __restrict__ x,
          const float* __restrict__ b1, const float* __restrict__ W2,
          const float* __restrict__ b2, const float* __restrict__ W3,
          const float* __restrict__ b3, float* __restrict__ out)
{
    const int n    = blockIdx.y;      // clique
    const int tile = blockIdx.x;      // batch tile
    const int tid  = threadIdx.x;
    const int wid  = tid >> 5;
    const int lane = tid & 31;
    const int g    = lane >> 2;       // mma groupID
    const int t    = lane & 3;        // mma threadID-in-group

    extern __shared__ char sm_raw[];
    unsigned* sW2T = (unsigned*)(sm_raw + OFF_W2T);  // [128 rows][72] (bf16x2 pairs, LDS.64 layout)
    unsigned* sH1  = (unsigned*)(sm_raw + OFF_H1);   // [256 rows][68]
    float*    sb1  = (float*)(sm_raw + OFF_B1);
    float*    sb2  = (float*)(sm_raw + OFF_B2);
    float*    sb3  = (float*)(sm_raw + OFF_B3);
    unsigned* sW3T = (unsigned*)(sm_raw + OFF_W3T);  // [8 rows][72]
    char*     sxo  = (char*)(sm_raw + OFF_XO);       // own states [b*4+j]
    char*     sxp  = (char*)(sm_raw + OFF_XP);       // parent states
    float*    slp  = (float*)(sm_raw + OFF_LP);      // 256 logp_obs

    // ---------------- stage weights / states into smem ----------------
    if (tid < HH) { sb1[tid] = b1[n * HH + tid]; sb2[tid] = b2[n * HH + tid]; }
    if (tid < 8)  sb3[tid] = b3[n * 8 + tid];
    {   // W2^T bf16, paired layout: 8B unit (o, kk, t) at o*72 + kk*8 + 2*(t ^ (o&3) ^ ((o>>2)&3))
        const float* gW2 = W2 + (size_t)n * HH * HH;
        #pragma unroll
        for (int it = 0; it < 16; it++) {
            int u = it * NTHREADS + tid;
            int o = u & 127, s = u >> 7;      // s in 0..31
            int kk = s >> 2, tt = s & 3;
            int ip0 = kk * 8 + tt, ip1 = ip0 + 4;
            __nv_bfloat162 p0 = __floats2bfloat162_rn(gW2[(2 * ip0) * HH + o],
                                                      gW2[(2 * ip0 + 1) * HH + o]);
            __nv_bfloat162 p1 = __floats2bfloat162_rn(gW2[(2 * ip1) * HH + o],
                                                      gW2[(2 * ip1 + 1) * HH + o]);
            int j = tt ^ (o & 3) ^ ((o >> 2) & 3);
            uint2 v; v.x = *(unsigned*)&p0; v.y = *(unsigned*)&p1;
            *(uint2*)(sW2T + o * W2STR + kk * 8 + 2 * j) = v;
        }
    }
    {   // W3^T bf16, same paired layout (8 rows)
        const float* gW3 = W3 + (size_t)n * HH * SQ;
        int o = tid & 7, s = tid >> 3;        // s in 0..31
        int kk = s >> 2, tt = s & 3;
        int ip0 = kk * 8 + tt, ip1 = ip0 + 4;
        __nv_bfloat162 p0 = __floats2bfloat162_rn(gW3[(2 * ip0) * SQ + o],
                                                  gW3[(2 * ip0 + 1) * SQ + o]);
        __nv_bfloat162 p1 = __floats2bfloat162_rn(gW3[(2 * ip1) * SQ + o],
                                                  gW3[(2 * ip1 + 1) * SQ + o]);
        int j = tt ^ (o & 3) ^ ((o >> 2) & 3);
        uint2 v; v.x = *(unsigned*)&p0; v.y = *(unsigned*)&p1;
        *(uint2*)(sW3T + o * W2STR + kk * 8 + 2 * j) = v;
    }
    {   // clique states (own + parent), byte-packed
        int bl = tid >> 2, j = tid & 3;
        const int* xr = x + (size_t)(tile * BT + bl) * (NCQ * KQ);
        sxo[tid] = (char)xr[n * KQ + j];
        sxp[tid] = (n > 0) ? (char)xr[(n - 1) * KQ + j] : 0;
    }
    __syncthreads();

    // ---------------- layer 1: sparse one-hot gather (W1 bf16 rows via L2) ----------------
    // warp w owns batch rows [8w, 8w+8) => h1 rows [32w, 32w+32)
    {
        const __nv_bfloat16* gW1 = g_w1bf + (size_t)n * 64 * HH;
        #pragma unroll
        for (int bi = 0; bi < 8; bi++) {
            int bl = wid * 8 + bi;
            float4 acc = ((const float4*)sb1)[lane];
            if (n > 0) {
                #pragma unroll
                for (int j = 0; j < 4; j++) {
                    int row = j * SQ + (int)sxp[bl * 4 + j];
                    uint2 u = __ldg((const uint2*)(gW1 + row * HH) + lane);
                    float2 f0 = __bfloat1622float2(*(__nv_bfloat162*)&u.x);
                    float2 f1 = __bfloat1622float2(*(__nv_bfloat162*)&u.y);
                    acc.x += f0.x; acc.y += f0.y; acc.z += f1.x; acc.w += f1.y;
                }
            }
            int r0 = bl * 4;
            #pragma unroll
            for (int k = 0; k < 4; k++) {
                if (k > 0) {    // incremental autoregressive prefix
                    int row = 32 + (k - 1) * SQ + (int)sxo[bl * 4 + (k - 1)];
                    uint2 u = __ldg((const uint2*)(gW1 + row * HH) + lane);
                    float2 f0 = __bfloat1622float2(*(__nv_bfloat162*)&u.x);
                    float2 f1 = __bfloat1622float2(*(__nv_bfloat162*)&u.y);
                    acc.x += f0.x; acc.y += f0.y; acc.z += f1.x; acc.w += f1.y;
                }
                __nv_bfloat162 p0 = __floats2bfloat162_rn(fmaxf(acc.x, 0.f), fmaxf(acc.y, 0.f));
                __nv_bfloat162 p1 = __floats2bfloat162_rn(fmaxf(acc.z, 0.f), fmaxf(acc.w, 0.f));
                unsigned* dst = sH1 + (r0 + k) * H1STR + 2 * lane;
                dst[0] = *(unsigned*)&p0;
                dst[1] = *(unsigned*)&p1;
            }
        }
    }
    __syncwarp();   // each warp only reads its own 32 rows below

    const int jx  = t ^ (g & 3);                    // W2T LDS.64 swizzle base
    const int jx3 = t ^ (g & 3) ^ ((g >> 2) & 3);   // W3T row = g
    const int rb  = wid * 32;

    // ---------------- layers 2+3: 32 rows per warp, B fragments shared across 2 M-tiles ----
    float d[2][4] = {{0.f,0.f,0.f,0.f},{0.f,0.f,0.f,0.f}};  // layer-3 logits accumulators

    #pragma unroll
    for (int nh = 0; nh < 2; nh++) {                // layer-2 N halves (cols 0-63 / 64-127)
        float cc[2][8][4];
        #pragma unroll
        for (int mt = 0; mt < 2; mt++)
            #pragma unroll
            for (int nb = 0; nb < 8; nb++)
                #pragma unroll
                for (int q = 0; q < 4; q++) cc[mt][nb][q] = 0.f;

        #pragma unroll
        for (int kk = 0; kk < 8; kk++) {            // k-steps of 16
            unsigned a[2][4];
            #pragma unroll
            for (int mt = 0; mt < 2; mt++) {
                const unsigned* p0 = sH1 + (rb + mt * 16 + g) * H1STR + kk * 8 + t;
                a[mt][0] = p0[0];           a[mt][2] = p0[4];
                a[mt][1] = p0[8 * H1STR];   a[mt][3] = p0[8 * H1STR + 4];
            }
            #pragma unroll
            for (int nb = 0; nb < 8; nb++) {
                int ncol = nh * 64 + nb * 8 + g;
                int j = jx ^ ((2 * nb + (g >> 2)) & 3);
                uint2 bq = *(const uint2*)(sW2T + ncol * W2STR + kk * 8 + 2 * j);
                mma16816(cc[0][nb], a[0], bq.x, bq.y);
                mma16816(cc[1][nb], a[1], bq.x, bq.y);
            }
        }

        // epilogue: + b2, relu, pack to bf16 layer-3 A fragments (registers only)
        unsigned pA[2][16];
        #pragma unroll
        for (int nb = 0; nb < 8; nb++) {
            int col0 = nh * 64 + nb * 8 + 2 * t;
            float bb0 = sb2[col0], bb1 = sb2[col0 + 1];
            #pragma unroll
            for (int mt = 0; mt < 2; mt++) {
                float r0 = fmaxf(cc[mt][nb][0] + bb0, 0.f);
                float r1 = fmaxf(cc[mt][nb][1] + bb1, 0.f);
                float r2 = fmaxf(cc[mt][nb][2] + bb0, 0.f);
                float r3 = fmaxf(cc[mt][nb][3] + bb1, 0.f);
                __nv_bfloat162 q0 = __floats2bfloat162_rn(r0, r1);
                __nv_bfloat162 q1 = __floats2bfloat162_rn(r2, r3);
                pA[mt][2 * nb]     = *(unsigned*)&q0;    // rows g
                pA[mt][2 * nb + 1] = *(unsigned*)&q1;    // rows g+8
            }
        }

        // layer-3 partial accumulation over this half's 4 k-tiles
        #pragma unroll
        for (int kk2 = 0; kk2 < 4; kk2++) {
            int kkt = nh * 4 + kk2;
            uint2 bq = *(const uint2*)(sW3T + g * W2STR + kkt * 8 + 2 * jx3);
            #pragma unroll
            for (int mt = 0; mt < 2; mt++) {
                const unsigned a[4] = { pA[mt][4 * kk2], pA[mt][4 * kk2 + 1],
                                        pA[mt][4 * kk2 + 2], pA[mt][4 * kk2 + 3] };
                mma16816(d[mt], a, bq.x, bq.y);
            }
        }
    }

    // ---------------- log-softmax over S=8 (quad reduce) + observed-state gather ----------
    {
        float bb0 = sb3[2 * t], bb1 = sb3[2 * t + 1];
        #pragma unroll
        for (int mt = 0; mt < 2; mt++) {
            #pragma unroll
            for (int h = 0; h < 2; h++) {            // row g (h=0) / row g+8 (h=1)
                float l0 = d[mt][2 * h]     + bb0;   // state 2t
                float l1 = d[mt][2 * h + 1] + bb1;   // state 2t+1
                float mx = fmaxf(l0, l1);
                mx = fmaxf(mx, __shfl_xor_sync(0xffffffffu, mx, 1));
                mx = fmaxf(mx, __shfl_xor_sync(0xffffffffu, mx, 2));
                float sum = __expf(l0 - mx) + __expf(l1 - mx);
                sum += __shfl_xor_sync(0xffffffffu, sum, 1);
                sum += __shfl_xor_sync(0xffffffffu, sum, 2);
                float lse = mx + __logf(sum);
                int row = rb + mt * 16 + h * 8 + g;  // == b_local*4 + k
                int sobs = (int)sxo[row];
                if ((sobs >> 1) == t)
                    slp[row] = ((sobs & 1) ? l1 : l0) - lse;
            }
        }
    }
    __syncthreads();

    // ---------------- sum over K positions, write out[b, n] ----------------
    if (tid < BT) {
        float s = slp[4 * tid] + slp[4 * tid + 1] + slp[4 * tid + 2] + slp[4 * tid + 3];
        out[(size_t)(tile * BT + tid) * NCQ + n] = s;
    }
}

extern "C" void kernel_launch(void* const* d_in, const int* in_sizes, int n_in,
                              void* d_out, int out_size) {
    (void)in_sizes; (void)n_in; (void)out_size;
    // 1) convert W1 to bf16 scratch (2,097,152 float2 pairs / 256 = 8192 blocks)
    conv_w1_kernel<<<8192, 256>>>((const float*)d_in[1]);
    // 2) main kernel
    cudaFuncSetAttribute(jt_kernel, cudaFuncAttributeMaxDynamicSharedMemorySize, SMEM_BYTES);
    dim3 grid(NB / BT, NCQ);   // x = batch tile (fast) -> same-clique CTAs adjacent for L2 reuse
    jt_kernel<<<grid, NTHREADS, SMEM_BYTES>>>(
        (const int*)d_in[0], (const float*)d_in[2],
        (const float*)d_in[3], (const float*)d_in[4], (const float*)d_in[5],
        (const float*)d_in[6], (float*)d_out);
}